// round 6
// baseline (speedup 1.0000x reference)
#include <cuda_runtime.h>
#include <math_constants.h>

// GraphSAGE fused: masked-max aggregation + relu + concat + Linear.
// B=4, N=512, C=128, OUT=128, adj ~10% dense (0.0/1.0 floats).
//
// R6 (vs R4, 14.8us): aggregation identical; GEMM rebuilt as smem-tiled
// double-buffered loop:
//  - W staged per block in 8 tiles of [32 k x 128 o] (16 KB), coalesced
//    float4 LDG, double-buffered -> W latency hidden behind compute
//  - steady-state inner loop touches only smem (W coalesced LDS.32,
//    comb LDS.128 broadcast) + packed fma.rn.f32x2
//  - all scratch (agg bufs, W tiles, split-k partials) aliased in 32 KB

#define B_DIM 4
#define N_DIM 512
#define C_DIM 128
#define OUT_DIM 128
#define ROWS 8
#define THREADS 512
#define TILE_K 32
#define NTILES 8          // 256 / TILE_K

__global__ __launch_bounds__(THREADS)
void graphsage_fused_kernel(const float* __restrict__ adj,
                            const float* __restrict__ feat,
                            const float* __restrict__ W,
                            const float* __restrict__ bias,
                            float* __restrict__ out)
{
    __shared__ __align__(16) float combT[2 * C_DIM][ROWS];   // 8 KB persistent
    __shared__ __align__(16) char scr[32768];                // 32 KB aliased

    // aggregation-phase views
    float (*aggbuf)[2][C_DIM] = reinterpret_cast<float (*)[2][C_DIM]>(scr);
    unsigned short (*idxbuf)[264] =
        reinterpret_cast<unsigned short (*)[264]>(scr + 8192);
    // gemm-phase views
    float4 (*WsmV)[1024] = reinterpret_cast<float4 (*)[1024]>(scr);  // [2][1024]
    float (*Wsm)[TILE_K][OUT_DIM] =
        reinterpret_cast<float (*)[TILE_K][OUT_DIM]>(scr);
    float (*ps)[ROWS][OUT_DIM] =
        reinterpret_cast<float (*)[ROWS][OUT_DIM]>(scr);     // 3x4KB in buf0

    const int tid  = threadIdx.x;
    const int warp = tid >> 5;
    const int lane = tid & 31;
    const int row  = warp >> 1;
    const int half = warp & 1;

    const int block_row0 = blockIdx.x * ROWS;
    const int grow = block_row0 + row;
    const int b = grow >> 9;
    const int i = grow & (N_DIM - 1);

    const float* __restrict__ fb = feat + (size_t)b * N_DIM * C_DIM;
    const float4* __restrict__ Wv = reinterpret_cast<const float4*>(W);

    // ---------------- Phase 1a: compact neighbor indices ----------------
    const float* __restrict__ adjrow =
        adj + ((size_t)b * N_DIM + i) * N_DIM + half * (N_DIM / 2);
    unsigned short* __restrict__ myidx = idxbuf[warp];
    const unsigned lt = (1u << lane) - 1u;

    int total = 0;
    #pragma unroll
    for (int c = 0; c < N_DIM / 2; c += 128) {
        float4 a = reinterpret_cast<const float4*>(adjrow + c)[lane];
        const int cbase = half * (N_DIM / 2) + c + 4 * lane;
        {
            unsigned m = __ballot_sync(0xffffffffu, a.x > 0.0f);
            if (a.x > 0.0f) myidx[total + __popc(m & lt)] = (unsigned short)(cbase + 0);
            total += __popc(m);
        }
        {
            unsigned m = __ballot_sync(0xffffffffu, a.y > 0.0f);
            if (a.y > 0.0f) myidx[total + __popc(m & lt)] = (unsigned short)(cbase + 1);
            total += __popc(m);
        }
        {
            unsigned m = __ballot_sync(0xffffffffu, a.z > 0.0f);
            if (a.z > 0.0f) myidx[total + __popc(m & lt)] = (unsigned short)(cbase + 2);
            total += __popc(m);
        }
        {
            unsigned m = __ballot_sync(0xffffffffu, a.w > 0.0f);
            if (a.w > 0.0f) myidx[total + __popc(m & lt)] = (unsigned short)(cbase + 3);
            total += __popc(m);
        }
    }
    __syncwarp();

    // ---------------- Phase 1b: gather + running max, MLP=8 ----------------
    float4 acc0 = make_float4(-CUDART_INF_F, -CUDART_INF_F, -CUDART_INF_F, -CUDART_INF_F);
    float4 acc1 = acc0, acc2 = acc0, acc3 = acc0;

    if (total > 0) {
        const int padded = (total + 7) & ~7;
        unsigned short lastv = myidx[total - 1];
        __syncwarp();
        if (lane < padded - total) myidx[total + lane] = lastv;
        __syncwarp();

        const uint4* __restrict__ ivec = reinterpret_cast<const uint4*>(myidx);
        for (int k = 0; k < padded; k += 8) {
            uint4 I = ivec[k >> 3];
            int j0 =  I.x        & 0xffff;
            int j1 = (I.x >> 16) & 0xffff;
            int j2 =  I.y        & 0xffff;
            int j3 = (I.y >> 16) & 0xffff;
            int j4 =  I.z        & 0xffff;
            int j5 = (I.z >> 16) & 0xffff;
            int j6 =  I.w        & 0xffff;
            int j7 = (I.w >> 16) & 0xffff;

            float4 f0 = reinterpret_cast<const float4*>(fb + (size_t)j0 * C_DIM)[lane];
            float4 f1 = reinterpret_cast<const float4*>(fb + (size_t)j1 * C_DIM)[lane];
            float4 f2 = reinterpret_cast<const float4*>(fb + (size_t)j2 * C_DIM)[lane];
            float4 f3 = reinterpret_cast<const float4*>(fb + (size_t)j3 * C_DIM)[lane];
            float4 f4 = reinterpret_cast<const float4*>(fb + (size_t)j4 * C_DIM)[lane];
            float4 f5 = reinterpret_cast<const float4*>(fb + (size_t)j5 * C_DIM)[lane];
            float4 f6 = reinterpret_cast<const float4*>(fb + (size_t)j6 * C_DIM)[lane];
            float4 f7 = reinterpret_cast<const float4*>(fb + (size_t)j7 * C_DIM)[lane];

            acc0.x = fmaxf(acc0.x, f0.x); acc0.y = fmaxf(acc0.y, f0.y);
            acc0.z = fmaxf(acc0.z, f0.z); acc0.w = fmaxf(acc0.w, f0.w);
            acc1.x = fmaxf(acc1.x, f1.x); acc1.y = fmaxf(acc1.y, f1.y);
            acc1.z = fmaxf(acc1.z, f1.z); acc1.w = fmaxf(acc1.w, f1.w);
            acc2.x = fmaxf(acc2.x, f2.x); acc2.y = fmaxf(acc2.y, f2.y);
            acc2.z = fmaxf(acc2.z, f2.z); acc2.w = fmaxf(acc2.w, f2.w);
            acc3.x = fmaxf(acc3.x, f3.x); acc3.y = fmaxf(acc3.y, f3.y);
            acc3.z = fmaxf(acc3.z, f3.z); acc3.w = fmaxf(acc3.w, f3.w);

            acc0.x = fmaxf(acc0.x, f4.x); acc0.y = fmaxf(acc0.y, f4.y);
            acc0.z = fmaxf(acc0.z, f4.z); acc0.w = fmaxf(acc0.w, f4.w);
            acc1.x = fmaxf(acc1.x, f5.x); acc1.y = fmaxf(acc1.y, f5.y);
            acc1.z = fmaxf(acc1.z, f5.z); acc1.w = fmaxf(acc1.w, f5.w);
            acc2.x = fmaxf(acc2.x, f6.x); acc2.y = fmaxf(acc2.y, f6.y);
            acc2.z = fmaxf(acc2.z, f6.z); acc2.w = fmaxf(acc2.w, f6.w);
            acc3.x = fmaxf(acc3.x, f7.x); acc3.y = fmaxf(acc3.y, f7.y);
            acc3.z = fmaxf(acc3.z, f7.z); acc3.w = fmaxf(acc3.w, f7.w);
        }
    }

    float4 accA;
    accA.x = fmaxf(fmaxf(acc0.x, acc1.x), fmaxf(acc2.x, acc3.x));
    accA.y = fmaxf(fmaxf(acc0.y, acc1.y), fmaxf(acc2.y, acc3.y));
    accA.z = fmaxf(fmaxf(acc0.z, acc1.z), fmaxf(acc2.z, acc3.z));
    accA.w = fmaxf(fmaxf(acc0.w, acc1.w), fmaxf(acc2.w, acc3.w));
    reinterpret_cast<float4*>(&aggbuf[row][half][0])[lane] = accA;

    // prefetch W tile 0 (arrives while phase 1c runs)
    float4 pre0 = Wv[tid];
    float4 pre1 = Wv[tid + 512];

    __syncthreads();

    // ---- Phase 1c: build combT (feature copy + combine halves + relu) ----
    {
        const int r  = tid & 7;
        const int c8 = tid >> 3;
        const int gr = block_row0 + r;
        const int rb = gr >> 9;
        const int ri = gr & (N_DIM - 1);
        const float* __restrict__ frow =
            feat + ((size_t)rb * N_DIM + ri) * C_DIM;
        #pragma unroll
        for (int j = 0; j < 2; ++j) {
            const int c = c8 + 64 * j;
            combT[c][r] = frow[c];
            combT[C_DIM + c][r] =
                fmaxf(0.0f, fmaxf(aggbuf[r][0][c], aggbuf[r][1][c]));
        }
    }
    __syncthreads();

    // stage W tile 0 into buf 0
    WsmV[0][tid]       = pre0;
    WsmV[0][tid + 512] = pre1;
    __syncthreads();

    // ---------------- Phase 2: smem-tiled GEMM ----------------
    // thread t: o = t&127, g = t>>7; per tile of 32 k, group g handles
    // k-subrange [g*8, g*8+8). Accumulates 8 rows x 1 col across all tiles.
    const int o = tid & (OUT_DIM - 1);
    const int g = tid >> 7;

    unsigned long long a01 = 0ull, a23 = 0ull, a45 = 0ull, a67 = 0ull;

    #pragma unroll
    for (int t = 0; t < NTILES; ++t) {
        const int buf = t & 1;

        // prefetch next tile (global, coalesced) while computing this one
        float4 n0, n1;
        if (t < NTILES - 1) {
            n0 = Wv[(t + 1) * 1024 + tid];
            n1 = Wv[(t + 1) * 1024 + tid + 512];
        }

        const float* __restrict__ wp = &Wsm[buf][g * 8][o];
        const float* __restrict__ cb = &combT[t * TILE_K + g * 8][0];

        #pragma unroll
        for (int kk = 0; kk < 8; ++kk) {
            float w = wp[kk * OUT_DIM];
            unsigned long long wpk;
            asm("mov.b64 %0, {%1, %1};" : "=l"(wpk) : "f"(w));

            const double2 q0 = *reinterpret_cast<const double2*>(cb + kk * 8);
            const double2 q1 = *reinterpret_cast<const double2*>(cb + kk * 8 + 4);
            unsigned long long p01 = __double_as_longlong(q0.x);
            unsigned long long p23 = __double_as_longlong(q0.y);
            unsigned long long p45 = __double_as_longlong(q1.x);
            unsigned long long p67 = __double_as_longlong(q1.y);

            asm("fma.rn.f32x2 %0, %1, %2, %0;" : "+l"(a01) : "l"(p01), "l"(wpk));
            asm("fma.rn.f32x2 %0, %1, %2, %0;" : "+l"(a23) : "l"(p23), "l"(wpk));
            asm("fma.rn.f32x2 %0, %1, %2, %0;" : "+l"(a45) : "l"(p45), "l"(wpk));
            asm("fma.rn.f32x2 %0, %1, %2, %0;" : "+l"(a67) : "l"(p67), "l"(wpk));
        }

        if (t < NTILES - 1) {
            // safe: nobody reads buf (1-buf target) since the prev sync
            WsmV[1 - buf][tid]       = n0;
            WsmV[1 - buf][tid + 512] = n1;
            __syncthreads();
        }
    }

    float r0, r1, r2, r3, r4, r5, r6, r7;
    asm("mov.b64 {%0, %1}, %2;" : "=f"(r0), "=f"(r1) : "l"(a01));
    asm("mov.b64 {%0, %1}, %2;" : "=f"(r2), "=f"(r3) : "l"(a23));
    asm("mov.b64 {%0, %1}, %2;" : "=f"(r4), "=f"(r5) : "l"(a45));
    asm("mov.b64 {%0, %1}, %2;" : "=f"(r6), "=f"(r7) : "l"(a67));

    // split-k reduce via ps (aliased on W buf 0; last tile computed from buf 1,
    // buf 0 reads all completed before the sync at end of tile 6)
    if (g != 0) {
        float* p = &ps[g - 1][0][o];
        p[0 * OUT_DIM] = r0;  p[1 * OUT_DIM] = r1;
        p[2 * OUT_DIM] = r2;  p[3 * OUT_DIM] = r3;
        p[4 * OUT_DIM] = r4;  p[5 * OUT_DIM] = r5;
        p[6 * OUT_DIM] = r6;  p[7 * OUT_DIM] = r7;
    }
    __syncthreads();
    if (g == 0) {
        const float bv = bias[o];
        const float* p0 = &ps[0][0][o];
        const float* p1 = &ps[1][0][o];
        const float* p2 = &ps[2][0][o];
        float* __restrict__ op = out + (size_t)block_row0 * OUT_DIM + o;
        op[0 * OUT_DIM] = r0 + p0[0 * OUT_DIM] + p1[0 * OUT_DIM] + p2[0 * OUT_DIM] + bv;
        op[1 * OUT_DIM] = r1 + p0[1 * OUT_DIM] + p1[1 * OUT_DIM] + p2[1 * OUT_DIM] + bv;
        op[2 * OUT_DIM] = r2 + p0[2 * OUT_DIM] + p1[2 * OUT_DIM] + p2[2 * OUT_DIM] + bv;
        op[3 * OUT_DIM] = r3 + p0[3 * OUT_DIM] + p1[3 * OUT_DIM] + p2[3 * OUT_DIM] + bv;
        op[4 * OUT_DIM] = r4 + p0[4 * OUT_DIM] + p1[4 * OUT_DIM] + p2[4 * OUT_DIM] + bv;
        op[5 * OUT_DIM] = r5 + p0[5 * OUT_DIM] + p1[5 * OUT_DIM] + p2[5 * OUT_DIM] + bv;
        op[6 * OUT_DIM] = r6 + p0[6 * OUT_DIM] + p1[6 * OUT_DIM] + p2[6 * OUT_DIM] + bv;
        op[7 * OUT_DIM] = r7 + p0[7 * OUT_DIM] + p1[7 * OUT_DIM] + p2[7 * OUT_DIM] + bv;
    }
}

extern "C" void kernel_launch(void* const* d_in, const int* in_sizes, int n_in,
                              void* d_out, int out_size)
{
    (void)in_sizes; (void)n_in; (void)out_size;
    const float* adj  = (const float*)d_in[0];   // [B,N,N]
    const float* feat = (const float*)d_in[1];   // [B,N,C]
    const float* W    = (const float*)d_in[2];   // [2C,OUT]
    const float* bias = (const float*)d_in[3];   // [OUT]
    float* out        = (float*)d_out;           // [B,N,OUT]

    dim3 grid((B_DIM * N_DIM) / ROWS);
    dim3 block(THREADS);
    graphsage_fused_kernel<<<grid, block>>>(adj, feat, W, bias, out);
}

// round 7
// speedup vs baseline: 1.6610x; 1.6610x over previous
#include <cuda_runtime.h>
#include <math_constants.h>

// GraphSAGE fused: masked-max aggregation + relu + concat + Linear.
// B=4, N=512, C=128, OUT=128, adj ~10% dense (0.0/1.0 floats).
//
// R7 = R4 (best, 14.8us) + GEMM inner-loop software pipelining:
//  - W loaded in register batches of 8 (8 independent LDG.32 -> MLP=8),
//    next batch prefetched while current batch computes -> W L2 latency
//    hidden instead of exposed per-k (R5 showed regs=32 serialized LDGs).
//  - __launch_bounds__(512,2): reg budget ~64 so the pipeline buffers fit,
//    while keeping 2 blocks/SM (grid 256 = one full wave).

#define B_DIM 4
#define N_DIM 512
#define C_DIM 128
#define OUT_DIM 128
#define ROWS 8
#define THREADS 512

__global__ __launch_bounds__(THREADS, 2)
void graphsage_fused_kernel(const float* __restrict__ adj,
                            const float* __restrict__ feat,
                            const float* __restrict__ W,
                            const float* __restrict__ bias,
                            float* __restrict__ out)
{
    __shared__ __align__(16) float combT[2 * C_DIM][ROWS];          // 8 KB
    __shared__ __align__(16) char scratch[8192 + 16 * 264 * 2];     // 16.4 KB

    float (*aggbuf)[2][C_DIM] = reinterpret_cast<float (*)[2][C_DIM]>(scratch);
    unsigned short (*idxbuf)[264] =
        reinterpret_cast<unsigned short (*)[264]>(scratch + 8192);
    float* ps = reinterpret_cast<float*>(scratch);   // [3][ROWS][OUT] partials

    const int tid  = threadIdx.x;
    const int warp = tid >> 5;
    const int lane = tid & 31;
    const int row  = warp >> 1;
    const int half = warp & 1;

    const int block_row0 = blockIdx.x * ROWS;
    const int grow = block_row0 + row;
    const int b = grow >> 9;
    const int i = grow & (N_DIM - 1);

    const float* __restrict__ fb = feat + (size_t)b * N_DIM * C_DIM;

    // ---------------- Phase 1a: compact neighbor indices ----------------
    const float* __restrict__ adjrow =
        adj + ((size_t)b * N_DIM + i) * N_DIM + half * (N_DIM / 2);
    unsigned short* __restrict__ myidx = idxbuf[warp];
    const unsigned lt = (1u << lane) - 1u;

    int total = 0;
    #pragma unroll
    for (int c = 0; c < N_DIM / 2; c += 128) {
        float4 a = reinterpret_cast<const float4*>(adjrow + c)[lane];
        const int cbase = half * (N_DIM / 2) + c + 4 * lane;
        {
            unsigned m = __ballot_sync(0xffffffffu, a.x > 0.0f);
            if (a.x > 0.0f) myidx[total + __popc(m & lt)] = (unsigned short)(cbase + 0);
            total += __popc(m);
        }
        {
            unsigned m = __ballot_sync(0xffffffffu, a.y > 0.0f);
            if (a.y > 0.0f) myidx[total + __popc(m & lt)] = (unsigned short)(cbase + 1);
            total += __popc(m);
        }
        {
            unsigned m = __ballot_sync(0xffffffffu, a.z > 0.0f);
            if (a.z > 0.0f) myidx[total + __popc(m & lt)] = (unsigned short)(cbase + 2);
            total += __popc(m);
        }
        {
            unsigned m = __ballot_sync(0xffffffffu, a.w > 0.0f);
            if (a.w > 0.0f) myidx[total + __popc(m & lt)] = (unsigned short)(cbase + 3);
            total += __popc(m);
        }
    }
    __syncwarp();

    // ---------------- Phase 1b: gather + running max, MLP=8 ----------------
    float4 acc0 = make_float4(-CUDART_INF_F, -CUDART_INF_F, -CUDART_INF_F, -CUDART_INF_F);
    float4 acc1 = acc0, acc2 = acc0, acc3 = acc0;

    if (total > 0) {
        const int padded = (total + 7) & ~7;
        unsigned short lastv = myidx[total - 1];
        __syncwarp();
        if (lane < padded - total) myidx[total + lane] = lastv;
        __syncwarp();

        const uint4* __restrict__ ivec = reinterpret_cast<const uint4*>(myidx);
        for (int k = 0; k < padded; k += 8) {
            uint4 I = ivec[k >> 3];
            int j0 =  I.x        & 0xffff;
            int j1 = (I.x >> 16) & 0xffff;
            int j2 =  I.y        & 0xffff;
            int j3 = (I.y >> 16) & 0xffff;
            int j4 =  I.z        & 0xffff;
            int j5 = (I.z >> 16) & 0xffff;
            int j6 =  I.w        & 0xffff;
            int j7 = (I.w >> 16) & 0xffff;

            float4 f0 = reinterpret_cast<const float4*>(fb + (size_t)j0 * C_DIM)[lane];
            float4 f1 = reinterpret_cast<const float4*>(fb + (size_t)j1 * C_DIM)[lane];
            float4 f2 = reinterpret_cast<const float4*>(fb + (size_t)j2 * C_DIM)[lane];
            float4 f3 = reinterpret_cast<const float4*>(fb + (size_t)j3 * C_DIM)[lane];
            float4 f4 = reinterpret_cast<const float4*>(fb + (size_t)j4 * C_DIM)[lane];
            float4 f5 = reinterpret_cast<const float4*>(fb + (size_t)j5 * C_DIM)[lane];
            float4 f6 = reinterpret_cast<const float4*>(fb + (size_t)j6 * C_DIM)[lane];
            float4 f7 = reinterpret_cast<const float4*>(fb + (size_t)j7 * C_DIM)[lane];

            acc0.x = fmaxf(acc0.x, f0.x); acc0.y = fmaxf(acc0.y, f0.y);
            acc0.z = fmaxf(acc0.z, f0.z); acc0.w = fmaxf(acc0.w, f0.w);
            acc1.x = fmaxf(acc1.x, f1.x); acc1.y = fmaxf(acc1.y, f1.y);
            acc1.z = fmaxf(acc1.z, f1.z); acc1.w = fmaxf(acc1.w, f1.w);
            acc2.x = fmaxf(acc2.x, f2.x); acc2.y = fmaxf(acc2.y, f2.y);
            acc2.z = fmaxf(acc2.z, f2.z); acc2.w = fmaxf(acc2.w, f2.w);
            acc3.x = fmaxf(acc3.x, f3.x); acc3.y = fmaxf(acc3.y, f3.y);
            acc3.z = fmaxf(acc3.z, f3.z); acc3.w = fmaxf(acc3.w, f3.w);

            acc0.x = fmaxf(acc0.x, f4.x); acc0.y = fmaxf(acc0.y, f4.y);
            acc0.z = fmaxf(acc0.z, f4.z); acc0.w = fmaxf(acc0.w, f4.w);
            acc1.x = fmaxf(acc1.x, f5.x); acc1.y = fmaxf(acc1.y, f5.y);
            acc1.z = fmaxf(acc1.z, f5.z); acc1.w = fmaxf(acc1.w, f5.w);
            acc2.x = fmaxf(acc2.x, f6.x); acc2.y = fmaxf(acc2.y, f6.y);
            acc2.z = fmaxf(acc2.z, f6.z); acc2.w = fmaxf(acc2.w, f6.w);
            acc3.x = fmaxf(acc3.x, f7.x); acc3.y = fmaxf(acc3.y, f7.y);
            acc3.z = fmaxf(acc3.z, f7.z); acc3.w = fmaxf(acc3.w, f7.w);
        }
    }

    float4 accA;
    accA.x = fmaxf(fmaxf(acc0.x, acc1.x), fmaxf(acc2.x, acc3.x));
    accA.y = fmaxf(fmaxf(acc0.y, acc1.y), fmaxf(acc2.y, acc3.y));
    accA.z = fmaxf(fmaxf(acc0.z, acc1.z), fmaxf(acc2.z, acc3.z));
    accA.w = fmaxf(fmaxf(acc0.w, acc1.w), fmaxf(acc2.w, acc3.w));
    reinterpret_cast<float4*>(&aggbuf[row][half][0])[lane] = accA;

    __syncthreads();

    // ---- Phase 1c: build combT (feature copy + combine halves + relu) ----
    {
        const int r  = tid & 7;
        const int c8 = tid >> 3;
        const int gr = block_row0 + r;
        const int rb = gr >> 9;
        const int ri = gr & (N_DIM - 1);
        const float* __restrict__ frow =
            feat + ((size_t)rb * N_DIM + ri) * C_DIM;
        #pragma unroll
        for (int j = 0; j < 2; ++j) {
            const int c = c8 + 64 * j;
            combT[c][r] = frow[c];
            combT[C_DIM + c][r] =
                fmaxf(0.0f, fmaxf(aggbuf[r][0][c], aggbuf[r][1][c]));
        }
    }
    __syncthreads();

    // ---------------- Phase 2: fused linear layer ----------------
    // thread t: o = t&127, ks = t>>7 (4-way k-split, 64 k each).
    // 8 rows x 1 col per thread. W loaded in register-pipelined batches
    // of 8 (MLP=8), next batch prefetched during current batch's compute.
    {
        const int o  = tid & (OUT_DIM - 1);
        const int ks = tid >> 7;

        const float* __restrict__ wp = W + (size_t)(ks * 64) * OUT_DIM + o;
        const float* __restrict__ cb = &combT[ks * 64][0];

        unsigned long long a01 = 0ull, a23 = 0ull, a45 = 0ull, a67 = 0ull;

        float wbuf[8];
        #pragma unroll
        for (int j = 0; j < 8; ++j) wbuf[j] = wp[(size_t)j * OUT_DIM];

        #pragma unroll
        for (int kb = 0; kb < 64; kb += 8) {
            float wnext[8];
            if (kb < 56) {
                #pragma unroll
                for (int j = 0; j < 8; ++j)
                    wnext[j] = wp[(size_t)(kb + 8 + j) * OUT_DIM];
            }

            #pragma unroll
            for (int j = 0; j < 8; ++j) {
                unsigned long long wpk;
                asm("mov.b64 %0, {%1, %1};" : "=l"(wpk) : "f"(wbuf[j]));

                const float* cbk = cb + (kb + j) * 8;
                const double2 q0 = *reinterpret_cast<const double2*>(cbk);
                const double2 q1 = *reinterpret_cast<const double2*>(cbk + 4);
                unsigned long long p01 = __double_as_longlong(q0.x);
                unsigned long long p23 = __double_as_longlong(q0.y);
                unsigned long long p45 = __double_as_longlong(q1.x);
                unsigned long long p67 = __double_as_longlong(q1.y);

                asm("fma.rn.f32x2 %0, %1, %2, %0;" : "+l"(a01) : "l"(p01), "l"(wpk));
                asm("fma.rn.f32x2 %0, %1, %2, %0;" : "+l"(a23) : "l"(p23), "l"(wpk));
                asm("fma.rn.f32x2 %0, %1, %2, %0;" : "+l"(a45) : "l"(p45), "l"(wpk));
                asm("fma.rn.f32x2 %0, %1, %2, %0;" : "+l"(a67) : "l"(p67), "l"(wpk));
            }

            if (kb < 56) {
                #pragma unroll
                for (int j = 0; j < 8; ++j) wbuf[j] = wnext[j];
            }
        }

        float r0, r1, r2, r3, r4, r5, r6, r7;
        asm("mov.b64 {%0, %1}, %2;" : "=f"(r0), "=f"(r1) : "l"(a01));
        asm("mov.b64 {%0, %1}, %2;" : "=f"(r2), "=f"(r3) : "l"(a23));
        asm("mov.b64 {%0, %1}, %2;" : "=f"(r4), "=f"(r5) : "l"(a45));
        asm("mov.b64 {%0, %1}, %2;" : "=f"(r6), "=f"(r7) : "l"(a67));

        if (ks != 0) {
            float* p = ps + (size_t)(ks - 1) * ROWS * OUT_DIM + o;
            p[0 * OUT_DIM] = r0;  p[1 * OUT_DIM] = r1;
            p[2 * OUT_DIM] = r2;  p[3 * OUT_DIM] = r3;
            p[4 * OUT_DIM] = r4;  p[5 * OUT_DIM] = r5;
            p[6 * OUT_DIM] = r6;  p[7 * OUT_DIM] = r7;
        }
        __syncthreads();
        if (ks == 0) {
            const float bv = bias[o];
            const float* p0 = ps + o;
            const float* p1 = ps + ROWS * OUT_DIM + o;
            const float* p2 = ps + 2 * ROWS * OUT_DIM + o;
            float* __restrict__ op = out + (size_t)block_row0 * OUT_DIM + o;
            op[0 * OUT_DIM] = r0 + p0[0 * OUT_DIM] + p1[0 * OUT_DIM] + p2[0 * OUT_DIM] + bv;
            op[1 * OUT_DIM] = r1 + p0[1 * OUT_DIM] + p1[1 * OUT_DIM] + p2[1 * OUT_DIM] + bv;
            op[2 * OUT_DIM] = r2 + p0[2 * OUT_DIM] + p1[2 * OUT_DIM] + p2[2 * OUT_DIM] + bv;
            op[3 * OUT_DIM] = r3 + p0[3 * OUT_DIM] + p1[3 * OUT_DIM] + p2[3 * OUT_DIM] + bv;
            op[4 * OUT_DIM] = r4 + p0[4 * OUT_DIM] + p1[4 * OUT_DIM] + p2[4 * OUT_DIM] + bv;
            op[5 * OUT_DIM] = r5 + p0[5 * OUT_DIM] + p1[5 * OUT_DIM] + p2[5 * OUT_DIM] + bv;
            op[6 * OUT_DIM] = r6 + p0[6 * OUT_DIM] + p1[6 * OUT_DIM] + p2[6 * OUT_DIM] + bv;
            op[7 * OUT_DIM] = r7 + p0[7 * OUT_DIM] + p1[7 * OUT_DIM] + p2[7 * OUT_DIM] + bv;
        }
    }
}

extern "C" void kernel_launch(void* const* d_in, const int* in_sizes, int n_in,
                              void* d_out, int out_size)
{
    (void)in_sizes; (void)n_in; (void)out_size;
    const float* adj  = (const float*)d_in[0];   // [B,N,N]
    const float* feat = (const float*)d_in[1];   // [B,N,C]
    const float* W    = (const float*)d_in[2];   // [2C,OUT]
    const float* bias = (const float*)d_in[3];   // [OUT]
    float* out        = (float*)d_out;           // [B,N,OUT]

    dim3 grid((B_DIM * N_DIM) / ROWS);
    dim3 block(THREADS);
    graphsage_fused_kernel<<<grid, block>>>(adj, feat, W, bias, out);
}